// round 3
// baseline (speedup 1.0000x reference)
#include <cuda_runtime.h>
#include <math.h>

// ---------------- consolidated scratch (single symbol, ~277MB) -------------
#define OFF_LN      0ull                      // 8200*768   = 6,297,600
#define OFF_QKV     6297600ull                // 8200*2304  = 18,892,800
#define OFF_ATT     25190400ull               // 8200*768   = 6,297,600
#define OFF_RES     31488000ull               // 8200*768   = 6,297,600
#define OFF_XT      37785600ull               // 8192*768   = 6,291,456
#define OFF_BIAS    44077056ull               // 12*1025*1025 -> 12,607,504 (padded)
#define OFF_H       56684560ull               // 4097*3072  = 12,585,984
#define SCRATCH_TOTAL 69270544ull
__device__ float g_scratch[SCRATCH_TOTAL];

__device__ __forceinline__ float gelu_exact(float x){
    return 0.5f*x*(1.0f+erff(x*0.70710678118654752440f));
}

// ---------------- layernorm with gather modes ------------------------------
__global__ __launch_bounds__(256) void ln_kernel(
    const float* __restrict__ src, const float* __restrict__ xsrc,
    float* __restrict__ dst, const float* __restrict__ g, const float* __restrict__ b,
    int mode)
{
    __shared__ float red[8];
    int r = blockIdx.x;
    int t = threadIdx.x;
    int lane = t & 31, warp = t >> 5;
    const float* in; size_t base;
    if (mode == 0){ in = src; base = (size_t)r*768u; }
    else if (mode == 1){ int bb = r>>12; int j = r & 4095; in = xsrc; base = (size_t)(bb*4097 + 1 + j)*768u; }
    else {
        int bt = r/1025, pos = r - bt*1025;
        int bb = bt>>2, tt = bt&3;
        if (pos == 0){ in = xsrc; base = (size_t)(bb*4097)*768u; }
        else { int n = pos-1; in = src; base = (size_t)(bb*4096 + n*4 + tt)*768u; }
    }
    float v0 = in[base+t], v1 = in[base+t+256], v2 = in[base+t+512];
    float s = v0+v1+v2;
    #pragma unroll
    for (int o=16;o>0;o>>=1) s += __shfl_xor_sync(0xffffffffu, s, o);
    if (lane==0) red[warp]=s;
    __syncthreads();
    if (warp==0){
        float w = red[lane&7];
        #pragma unroll
        for (int o=4;o>0;o>>=1) w += __shfl_xor_sync(0xffffffffu, w, o);
        if (lane==0) red[0]=w;
    }
    __syncthreads();
    float mean = red[0]*(1.0f/768.0f);
    float d0=v0-mean, d1=v1-mean, d2=v2-mean;
    float q = d0*d0+d1*d1+d2*d2;
    #pragma unroll
    for (int o=16;o>0;o>>=1) q += __shfl_xor_sync(0xffffffffu, q, o);
    __syncthreads();
    if (lane==0) red[warp]=q;
    __syncthreads();
    if (warp==0){
        float w = red[lane&7];
        #pragma unroll
        for (int o=4;o>0;o>>=1) w += __shfl_xor_sync(0xffffffffu, w, o);
        if (lane==0) red[0]=w;
    }
    __syncthreads();
    float var = red[0]*(1.0f/768.0f);
    float rstd = rsqrtf(var + 1e-5f);
    size_t ob = (size_t)r*768u;
    dst[ob+t]     = d0*rstd*g[t]     + b[t];
    dst[ob+t+256] = d1*rstd*g[t+256] + b[t+256];
    dst[ob+t+512] = d2*rstd*g[t+512] + b[t+512];
}

// ---------------- generic fp32 SGEMM: C[M,N] = A[M,K] @ W[N,K]^T -----------
__global__ __launch_bounds__(256) void sgemm_nt(
    const float* __restrict__ A, const float* __restrict__ W,
    const float* __restrict__ bias, float* __restrict__ C,
    int M, int N, int K,
    const float* __restrict__ res, int resMode, int doGelu)
{
    __shared__ float As[8][128];
    __shared__ float Ws[8][128];
    int tid = threadIdx.x;
    int tx = tid & 15, ty = tid >> 4;
    int bm = blockIdx.y*128, bn = blockIdx.x*128;
    int lr = tid >> 1;
    int lc = (tid & 1)*4;
    float acc[8][8];
    #pragma unroll
    for (int i=0;i<8;i++)
        #pragma unroll
        for (int j=0;j<8;j++) acc[i][j]=0.f;

    int gmA = bm + lr;
    int gnW = bn + lr;
    const float* Ap = A + (size_t)gmA*K + lc;
    const float* Wp = W + (size_t)gnW*K + lc;
    bool va = (gmA < M);
    int nK = K >> 3;
    for (int kt=0; kt<nK; ++kt){
        float4 a4 = va ? *(const float4*)(Ap) : make_float4(0.f,0.f,0.f,0.f);
        float4 w4 = *(const float4*)(Wp);
        As[lc+0][lr]=a4.x; As[lc+1][lr]=a4.y; As[lc+2][lr]=a4.z; As[lc+3][lr]=a4.w;
        Ws[lc+0][lr]=w4.x; Ws[lc+1][lr]=w4.y; Ws[lc+2][lr]=w4.z; Ws[lc+3][lr]=w4.w;
        __syncthreads();
        #pragma unroll
        for (int k=0;k<8;++k){
            float4 a0=*(const float4*)&As[k][ty*8], a1=*(const float4*)&As[k][ty*8+4];
            float4 b0=*(const float4*)&Ws[k][tx*8], b1=*(const float4*)&Ws[k][tx*8+4];
            float av[8]={a0.x,a0.y,a0.z,a0.w,a1.x,a1.y,a1.z,a1.w};
            float bv[8]={b0.x,b0.y,b0.z,b0.w,b1.x,b1.y,b1.z,b1.w};
            #pragma unroll
            for (int i=0;i<8;++i)
                #pragma unroll
                for (int j=0;j<8;++j) acc[i][j] += av[i]*bv[j];
        }
        __syncthreads();
        Ap += 8; Wp += 8;
    }
    #pragma unroll
    for (int i=0;i<8;++i){
        int m = bm + ty*8 + i;
        if (m >= M) break;
        const float* rrow = nullptr;
        if (resMode == 1) rrow = res + (size_t)m*N;
        else if (resMode == 2){ int bb = m>>12, j = m&4095; rrow = res + (size_t)(bb*4097+1+j)*N; }
        float* crow = C + (size_t)m*N;
        #pragma unroll
        for (int j=0;j<8;++j){
            int n = bn + tx*8 + j;
            float c = acc[i][j];
            if (bias) c += bias[n];
            if (doGelu) c = gelu_exact(c);
            if (rrow) c += rrow[n];
            crow[n] = c;
        }
    }
}

// ---------------- geometry bias -------------------------------------------
__global__ __launch_bounds__(256) void bias_kernel(
    const float* __restrict__ wg_w, const float* __restrict__ wg_b,
    float* __restrict__ bias)
{
    __shared__ float sw[768];
    __shared__ float sc[12];
    int t = threadIdx.x;
    for (int i=t;i<768;i+=256) sw[i]=wg_w[i];
    __syncthreads();
    if (t < 12){
        float s = wg_b[t];
        #pragma unroll
        for (int k=48;k<64;++k) s += sw[t*64+k];   // cos(0)=1 terms
        sc[t] = s;
    }
    __syncthreads();
    size_t idx = (size_t)blockIdx.x*256u + t;
    if (idx >= (size_t)1025u*1025u) return;
    int i = (int)(idx/1025u), j = (int)(idx - (size_t)i*1025u);
    if (i==0 || j==0){
        #pragma unroll
        for (int h=0;h<12;++h) bias[(size_t)h*1025u*1025u + idx] = 0.f;
        return;
    }
    int a = i-1, b2 = j-1;
    float fx = (float)((a>>5)-(b2>>5)) * (1.0f/32.0f);
    float fy = (float)((a&31)-(b2&31)) * (1.0f/32.0f);
    const float inv_wbox = 1.0f/1.03125f;
    float dx = logf(fmaxf(fabsf(fx*inv_wbox), 0.001f));
    float dy = logf(fmaxf(fabsf(fy*inv_wbox), 0.001f));
    const float dm[8] = {1.0f, 0.42169650342f, 0.1778279410f, 0.074989420933f,
                         0.03162277660f, 0.013335214322f, 0.0056234132519f, 0.0023713737057f};
    float sx[8], cx[8], sy[8], cy[8];
    #pragma unroll
    for (int k=0;k<8;++k){
        sincosf(100.0f*dx*dm[k], &sx[k], &cx[k]);
        sincosf(100.0f*dy*dm[k], &sy[k], &cy[k]);
    }
    #pragma unroll
    for (int h=0;h<12;++h){
        const float* w = sw + h*64;
        float acc = sc[h];
        #pragma unroll
        for (int k=0;k<8;++k)
            acc += sx[k]*w[k] + sy[k]*w[8+k] + cx[k]*w[32+k] + cy[k]*w[40+k];
        float wv = fmaxf(acc, 0.0f);
        bias[(size_t)h*1025u*1025u + idx] = logf(fmaxf(wv, 1e-6f));
    }
}

// ---------------- temporal attention (T=4): one warp per (seq, head) ------
__global__ __launch_bounds__(256) void temporal_attn_kernel(
    const float* __restrict__ qkv, float* __restrict__ out)
{
    int gw = (blockIdx.x*256 + threadIdx.x) >> 5;
    int lane = threadIdx.x & 31;
    if (gw >= 2048*12) return;
    int s = gw/12, h = gw - s*12;
    size_t base = (size_t)(s*4)*2304u + h*64 + lane*2;
    float2 q[4],k[4],v[4];
    #pragma unroll
    for (int i=0;i<4;++i){
        q[i] = *(const float2*)(qkv + base + (size_t)i*2304u);
        k[i] = *(const float2*)(qkv + base + (size_t)i*2304u + 768u);
        v[i] = *(const float2*)(qkv + base + (size_t)i*2304u + 1536u);
    }
    float sc[16];
    #pragma unroll
    for (int i=0;i<4;++i)
        #pragma unroll
        for (int j=0;j<4;++j)
            sc[i*4+j] = q[i].x*k[j].x + q[i].y*k[j].y;
    #pragma unroll
    for (int t2=0;t2<16;++t2)
        #pragma unroll
        for (int off=16; off>0; off>>=1)
            sc[t2] += __shfl_xor_sync(0xffffffffu, sc[t2], off);
    #pragma unroll
    for (int i=0;i<4;++i){
        float s0=sc[i*4+0]*0.125f, s1=sc[i*4+1]*0.125f, s2=sc[i*4+2]*0.125f, s3=sc[i*4+3]*0.125f;
        float m = fmaxf(fmaxf(s0,s1),fmaxf(s2,s3));
        float e0=expf(s0-m), e1=expf(s1-m), e2=expf(s2-m), e3=expf(s3-m);
        float inv = 1.0f/(e0+e1+e2+e3);
        float ox = (e0*v[0].x + e1*v[1].x + e2*v[2].x + e3*v[3].x)*inv;
        float oy = (e0*v[0].y + e1*v[1].y + e2*v[2].y + e3*v[3].y)*inv;
        float2 o; o.x = ox; o.y = oy;
        *(float2*)(out + (size_t)(s*4+i)*768u + h*64 + lane*2) = o;
    }
}

// ---------------- spatial flash attention ----------------------------------
// grid (17, 96): blockIdx.x = i-tile (64 rows), blockIdx.y = bt*12+h
// out[(bt*1025+i)*768 + h*64 + d] = softmax(QK^T*scale + bias) @ V
__global__ __launch_bounds__(256) void flash_attn_kernel(
    const float* __restrict__ qkv, const float* __restrict__ bias,
    float* __restrict__ out)
{
    extern __shared__ float sm[];
    float (*Qs)[68] = (float(*)[68])sm;            // [d][i]
    float (*Ks)[68] = (float(*)[68])(sm + 64*68);  // [d][j]
    float (*Vs)[68] = (float(*)[68])(sm + 2*64*68);// [j][d]
    float (*Ps)[68] = (float(*)[68])(sm + 3*64*68);// [i][j]
    int bh = blockIdx.y; int bt = bh/12, h = bh - bt*12;
    int i0 = blockIdx.x*64;
    int tid = threadIdx.x;
    int tx = tid & 15, ty = tid >> 4;

    // load Q tile, fold in 1/8 scale
    #pragma unroll
    for (int u=0; u<16; ++u){
        int idx = u*256 + tid;
        int dd = idx & 63, ii = idx >> 6;
        int gi = i0 + ii;
        Qs[dd][ii] = (gi < 1025) ? qkv[(size_t)(bt*1025+gi)*2304u + h*64 + dd]*0.125f : 0.f;
    }

    float m[4], l[4], acc[4][4];
    #pragma unroll
    for (int r=0;r<4;++r){ m[r]=-1e30f; l[r]=0.f;
        #pragma unroll
        for (int c=0;c<4;++c) acc[r][c]=0.f; }

    for (int j0=0; j0<1025; j0+=64){
        #pragma unroll
        for (int u=0; u<16; ++u){
            int idx = u*256 + tid;
            int dd = idx & 63, jj = idx >> 6;
            int gj = j0 + jj;
            bool v = (gj < 1025);
            Ks[dd][jj] = v ? qkv[(size_t)(bt*1025+gj)*2304u + 768u  + h*64 + dd] : 0.f;
            Vs[jj][dd] = v ? qkv[(size_t)(bt*1025+gj)*2304u + 1536u + h*64 + dd] : 0.f;
        }
        __syncthreads();

        // S tile: rows ty*4+r, cols tx*4+c
        float s[4][4];
        #pragma unroll
        for (int r=0;r<4;++r)
            #pragma unroll
            for (int c=0;c<4;++c) s[r][c]=0.f;
        #pragma unroll 8
        for (int k=0;k<64;++k){
            float4 q4 = *(const float4*)&Qs[k][ty*4];
            float4 k4 = *(const float4*)&Ks[k][tx*4];
            float qr[4]={q4.x,q4.y,q4.z,q4.w}, kc[4]={k4.x,k4.y,k4.z,k4.w};
            #pragma unroll
            for (int r=0;r<4;++r)
                #pragma unroll
                for (int c=0;c<4;++c) s[r][c] += qr[r]*kc[c];
        }
        // bias + masking
        #pragma unroll
        for (int r=0;r<4;++r){
            int gi = i0 + ty*4 + r;
            #pragma unroll
            for (int c=0;c<4;++c){
                int gj = j0 + tx*4 + c;
                if (gi < 1025 && gj < 1025)
                    s[r][c] += bias[((size_t)h*1025u + gi)*1025u + gj];
                else
                    s[r][c] = -1e30f;
            }
        }
        // online softmax: row reductions over c then over tx (within warp-half)
        #pragma unroll
        for (int r=0;r<4;++r){
            float rm = fmaxf(fmaxf(s[r][0],s[r][1]),fmaxf(s[r][2],s[r][3]));
            #pragma unroll
            for (int o=8;o>0;o>>=1) rm = fmaxf(rm, __shfl_xor_sync(0xffffffffu, rm, o));
            float mn = fmaxf(m[r], rm);
            float corr = __expf(m[r]-mn);
            m[r] = mn;
            float rs = 0.f;
            #pragma unroll
            for (int c=0;c<4;++c){ float p = __expf(s[r][c]-mn); s[r][c]=p; rs+=p; }
            #pragma unroll
            for (int o=8;o>0;o>>=1) rs += __shfl_xor_sync(0xffffffffu, rs, o);
            l[r] = l[r]*corr + rs;
            #pragma unroll
            for (int c=0;c<4;++c) acc[r][c] *= corr;
        }
        __syncthreads();   // all Ks reads done before Ps writes? (Ps separate array; this orders bias-phase smem safety + prepares Ps visibility)
        #pragma unroll
        for (int r=0;r<4;++r)
            *(float4*)&Ps[ty*4+r][tx*4] = make_float4(s[r][0],s[r][1],s[r][2],s[r][3]);
        __syncthreads();
        // acc += P @ V   (P broadcast by row, V float4 by column)
        #pragma unroll 8
        for (int jj=0;jj<64;++jj){
            float4 v4 = *(const float4*)&Vs[jj][tx*4];
            #pragma unroll
            for (int r=0;r<4;++r){
                float p = Ps[ty*4+r][jj];
                acc[r][0] += p*v4.x; acc[r][1] += p*v4.y;
                acc[r][2] += p*v4.z; acc[r][3] += p*v4.w;
            }
        }
        __syncthreads();
    }
    #pragma unroll
    for (int r=0;r<4;++r){
        int gi = i0 + ty*4 + r;
        if (gi < 1025){
            float inv = 1.0f/l[r];
            float4 o;
            o.x = acc[r][0]*inv; o.y = acc[r][1]*inv;
            o.z = acc[r][2]*inv; o.w = acc[r][3]*inv;
            *(float4*)&out[(size_t)(bt*1025+gi)*768u + h*64 + tx*4] = o;
        }
    }
}

// ---------------- combine: xout = concat(cls,xt) + concat(cls_out,res_s) ---
__global__ __launch_bounds__(256) void combine_kernel(
    const float* __restrict__ x, const float* __restrict__ xt,
    const float* __restrict__ res_s, float* __restrict__ out)
{
    size_t idx = (size_t)blockIdx.x*256u + threadIdx.x;
    if (idx >= (size_t)2u*4097u*768u) return;
    int c = (int)(idx % 768u);
    size_t row = idx / 768u;
    int b = (int)(row / 4097u);
    int rr = (int)(row - (size_t)b*4097u);
    float v;
    if (rr == 0){
        float s = 0.f;
        #pragma unroll
        for (int t2=0;t2<4;++t2)
            s += res_s[((size_t)((b*4+t2)*1025))*768u + c];
        v = x[row*768u + c] + 0.25f*s;
    } else {
        int qq = rr-1; int n = qq>>2, t2 = qq&3;
        v = xt[((size_t)(b*4096 + qq))*768u + c]
          + res_s[((size_t)((b*4+t2)*1025 + 1 + n))*768u + c];
    }
    out[row*768u + c] = v;
}

// ---------------- launcher -------------------------------------------------
extern "C" void kernel_launch(void* const* d_in, const int* in_sizes, int n_in,
                              void* d_out, int out_size)
{
    const float* x       = (const float*)d_in[0];
    const float* norm1_g = (const float*)d_in[1];
    const float* norm1_b = (const float*)d_in[2];
    const float* qkv_w   = (const float*)d_in[3];
    const float* proj_w  = (const float*)d_in[4];
    const float* proj_b  = (const float*)d_in[5];
    const float* wg_w    = (const float*)d_in[6];
    const float* wg_b    = (const float*)d_in[7];
    const float* tnorm1_g= (const float*)d_in[8];
    const float* tnorm1_b= (const float*)d_in[9];
    const float* tqkv_w  = (const float*)d_in[10];
    const float* tproj_w = (const float*)d_in[11];
    const float* tproj_b = (const float*)d_in[12];
    const float* tfc_w   = (const float*)d_in[13];
    const float* tfc_b   = (const float*)d_in[14];
    const float* norm2_g = (const float*)d_in[15];
    const float* norm2_b = (const float*)d_in[16];
    const float* fc1_w   = (const float*)d_in[17];
    const float* fc1_b   = (const float*)d_in[18];
    const float* fc2_w   = (const float*)d_in[19];
    const float* fc2_b   = (const float*)d_in[20];
    float* out = (float*)d_out;

    float* base = nullptr;
    cudaGetSymbolAddress((void**)&base, g_scratch);
    float* p_ln   = base + OFF_LN;
    float* p_qkv  = base + OFF_QKV;
    float* p_att  = base + OFF_ATT;
    float* p_res  = base + OFF_RES;
    float* p_xt   = base + OFF_XT;
    float* p_bias = base + OFF_BIAS;
    float* p_h    = base + OFF_H;

    const int FLASH_SMEM = 4*64*68*4;  // 69,632 B
    cudaFuncSetAttribute(flash_attn_kernel,
                         cudaFuncAttributeMaxDynamicSharedMemorySize, FLASH_SMEM);

    // ---- temporal branch ----
    ln_kernel<<<8192,256>>>(nullptr, x, p_ln, tnorm1_g, tnorm1_b, 1);
    sgemm_nt<<<dim3(18,64),256>>>(p_ln, tqkv_w, nullptr, p_qkv, 8192, 2304, 768, nullptr, 0, 0);
    temporal_attn_kernel<<<3072,256>>>(p_qkv, p_att);
    sgemm_nt<<<dim3(6,64),256>>>(p_att, tproj_w, tproj_b, p_res, 8192, 768, 768, nullptr, 0, 0);
    sgemm_nt<<<dim3(6,64),256>>>(p_res, tfc_w, tfc_b, p_xt, 8192, 768, 768, x, 2, 0); // xt = x[:,1:] + res

    // ---- spatial branch ----
    ln_kernel<<<8200,256>>>(p_xt, x, p_ln, norm1_g, norm1_b, 2);
    sgemm_nt<<<dim3(18,65),256>>>(p_ln, qkv_w, nullptr, p_qkv, 8200, 2304, 768, nullptr, 0, 0);
    bias_kernel<<<4105,256>>>(wg_w, wg_b, p_bias);
    flash_attn_kernel<<<dim3(17,96),256,FLASH_SMEM>>>(p_qkv, p_bias, p_att);
    sgemm_nt<<<dim3(6,65),256>>>(p_att, proj_w, proj_b, p_res, 8200, 768, 768, nullptr, 0, 0);
    combine_kernel<<<24582,256>>>(x, p_xt, p_res, out);

    // ---- MLP (chunked over 2x4097 rows to halve hidden buffer) ----
    ln_kernel<<<8194,256>>>(out, nullptr, p_ln, norm2_g, norm2_b, 0);
    for (int ch=0; ch<2; ++ch){
        size_t ro = (size_t)ch*4097u;
        sgemm_nt<<<dim3(24,33),256>>>(p_ln + ro*768u, fc1_w, fc1_b, p_h, 4097, 3072, 768, nullptr, 0, 1);
        sgemm_nt<<<dim3(6,33),256>>>(p_h, fc2_w, fc2_b, out + ro*768u, 4097, 768, 3072, out + ro*768u, 1, 0);
    }
}

// round 4
// speedup vs baseline: 1.0348x; 1.0348x over previous
#include <cuda_runtime.h>
#include <math.h>

// ---------------- consolidated scratch (single symbol, ~277MB) -------------
#define OFF_LN      0ull                      // 8200*768   = 6,297,600
#define OFF_QKV     6297600ull                // 8200*2304  = 18,892,800
#define OFF_ATT     25190400ull               // 8200*768   = 6,297,600
#define OFF_RES     31488000ull               // 8200*768   = 6,297,600
#define OFF_XT      37785600ull               // 8192*768   = 6,291,456
#define OFF_BIAS    44077056ull               // 12*1025*1025 -> 12,607,504 (padded)
#define OFF_H       56684560ull               // 4097*3072  = 12,585,984
#define SCRATCH_TOTAL 69270544ull
__device__ float g_scratch[SCRATCH_TOTAL];

__device__ __forceinline__ float gelu_exact(float x){
    return 0.5f*x*(1.0f+erff(x*0.70710678118654752440f));
}

// ---------------- packed f32x2 helpers (sm_103a dual-rate fp32 path) -------
__device__ __forceinline__ unsigned long long pack2(float lo, float hi){
    unsigned long long r;
    asm("mov.b64 %0, {%1, %2};" : "=l"(r) : "f"(lo), "f"(hi));
    return r;
}
__device__ __forceinline__ void fma2(unsigned long long &d, unsigned long long a, unsigned long long b){
    asm("fma.rn.f32x2 %0, %1, %2, %3;" : "=l"(d) : "l"(a), "l"(b), "l"(d));
}
__device__ __forceinline__ void mul2ip(unsigned long long &d, unsigned long long a){
    asm("mul.rn.f32x2 %0, %1, %2;" : "=l"(d) : "l"(d), "l"(a));
}
__device__ __forceinline__ void unpack2(unsigned long long v, float &lo, float &hi){
    asm("mov.b64 {%0, %1}, %2;" : "=f"(lo), "=f"(hi) : "l"(v));
}

// ---------------- layernorm with gather modes ------------------------------
__global__ __launch_bounds__(256) void ln_kernel(
    const float* __restrict__ src, const float* __restrict__ xsrc,
    float* __restrict__ dst, const float* __restrict__ g, const float* __restrict__ b,
    int mode)
{
    __shared__ float red[8];
    int r = blockIdx.x;
    int t = threadIdx.x;
    int lane = t & 31, warp = t >> 5;
    const float* in; size_t base;
    if (mode == 0){ in = src; base = (size_t)r*768u; }
    else if (mode == 1){ int bb = r>>12; int j = r & 4095; in = xsrc; base = (size_t)(bb*4097 + 1 + j)*768u; }
    else {
        int bt = r/1025, pos = r - bt*1025;
        int bb = bt>>2, tt = bt&3;
        if (pos == 0){ in = xsrc; base = (size_t)(bb*4097)*768u; }
        else { int n = pos-1; in = src; base = (size_t)(bb*4096 + n*4 + tt)*768u; }
    }
    float v0 = in[base+t], v1 = in[base+t+256], v2 = in[base+t+512];
    float s = v0+v1+v2;
    #pragma unroll
    for (int o=16;o>0;o>>=1) s += __shfl_xor_sync(0xffffffffu, s, o);
    if (lane==0) red[warp]=s;
    __syncthreads();
    if (warp==0){
        float w = red[lane&7];
        #pragma unroll
        for (int o=4;o>0;o>>=1) w += __shfl_xor_sync(0xffffffffu, w, o);
        if (lane==0) red[0]=w;
    }
    __syncthreads();
    float mean = red[0]*(1.0f/768.0f);
    float d0=v0-mean, d1=v1-mean, d2=v2-mean;
    float q = d0*d0+d1*d1+d2*d2;
    #pragma unroll
    for (int o=16;o>0;o>>=1) q += __shfl_xor_sync(0xffffffffu, q, o);
    __syncthreads();
    if (lane==0) red[warp]=q;
    __syncthreads();
    if (warp==0){
        float w = red[lane&7];
        #pragma unroll
        for (int o=4;o>0;o>>=1) w += __shfl_xor_sync(0xffffffffu, w, o);
        if (lane==0) red[0]=w;
    }
    __syncthreads();
    float var = red[0]*(1.0f/768.0f);
    float rstd = rsqrtf(var + 1e-5f);
    size_t ob = (size_t)r*768u;
    dst[ob+t]     = d0*rstd*g[t]     + b[t];
    dst[ob+t+256] = d1*rstd*g[t+256] + b[t+256];
    dst[ob+t+512] = d2*rstd*g[t+512] + b[t+512];
}

// ---------------- fp32 SGEMM via packed f32x2: C = A[M,K] @ W[N,K]^T -------
__global__ __launch_bounds__(256,2) void sgemm_nt(
    const float* __restrict__ A, const float* __restrict__ W,
    const float* __restrict__ bias, float* __restrict__ C,
    int M, int N, int K,
    const float* __restrict__ res, int resMode, int doGelu)
{
    __shared__ float As[8][128];
    __shared__ float Ws[8][128];
    int tid = threadIdx.x;
    int tx = tid & 15, ty = tid >> 4;
    int bm = blockIdx.y*128, bn = blockIdx.x*128;
    int lr = tid >> 1;
    int lc = (tid & 1)*4;
    unsigned long long acc[8][4];   // packed pairs along n
    #pragma unroll
    for (int i=0;i<8;i++)
        #pragma unroll
        for (int j=0;j<4;j++) acc[i][j]=0ull;

    int gmA = bm + lr;
    int gnW = bn + lr;
    const float* Ap = A + (size_t)gmA*K + lc;
    const float* Wp = W + (size_t)gnW*K + lc;
    bool va = (gmA < M);
    int nK = K >> 3;
    for (int kt=0; kt<nK; ++kt){
        float4 a4 = va ? *(const float4*)(Ap) : make_float4(0.f,0.f,0.f,0.f);
        float4 w4 = *(const float4*)(Wp);
        As[lc+0][lr]=a4.x; As[lc+1][lr]=a4.y; As[lc+2][lr]=a4.z; As[lc+3][lr]=a4.w;
        Ws[lc+0][lr]=w4.x; Ws[lc+1][lr]=w4.y; Ws[lc+2][lr]=w4.z; Ws[lc+3][lr]=w4.w;
        __syncthreads();
        #pragma unroll
        for (int k=0;k<8;++k){
            float4 a0=*(const float4*)&As[k][ty*8], a1=*(const float4*)&As[k][ty*8+4];
            float4 b0=*(const float4*)&Ws[k][tx*8], b1=*(const float4*)&Ws[k][tx*8+4];
            unsigned long long bb[4];
            bb[0]=pack2(b0.x,b0.y); bb[1]=pack2(b0.z,b0.w);
            bb[2]=pack2(b1.x,b1.y); bb[3]=pack2(b1.z,b1.w);
            float av[8]={a0.x,a0.y,a0.z,a0.w,a1.x,a1.y,a1.z,a1.w};
            #pragma unroll
            for (int i=0;i<8;++i){
                unsigned long long aa = pack2(av[i], av[i]);
                #pragma unroll
                for (int j=0;j<4;++j) fma2(acc[i][j], aa, bb[j]);
            }
        }
        __syncthreads();
        Ap += 8; Wp += 8;
    }
    #pragma unroll
    for (int i=0;i<8;++i){
        int m = bm + ty*8 + i;
        if (m >= M) break;
        const float* rrow = nullptr;
        if (resMode == 1) rrow = res + (size_t)m*N;
        else if (resMode == 2){ int bb2 = m>>12, j = m&4095; rrow = res + (size_t)(bb2*4097+1+j)*N; }
        float* crow = C + (size_t)m*N;
        int n0 = bn + tx*8;
        float c[8];
        #pragma unroll
        for (int j=0;j<4;++j) unpack2(acc[i][j], c[2*j], c[2*j+1]);
        if (bias){
            float4 bsa = *(const float4*)&bias[n0];
            float4 bsb = *(const float4*)&bias[n0+4];
            c[0]+=bsa.x;c[1]+=bsa.y;c[2]+=bsa.z;c[3]+=bsa.w;
            c[4]+=bsb.x;c[5]+=bsb.y;c[6]+=bsb.z;c[7]+=bsb.w;
        }
        if (doGelu){
            #pragma unroll
            for (int j=0;j<8;++j) c[j] = gelu_exact(c[j]);
        }
        if (rrow){
            float4 ra = *(const float4*)&rrow[n0];
            float4 rb = *(const float4*)&rrow[n0+4];
            c[0]+=ra.x;c[1]+=ra.y;c[2]+=ra.z;c[3]+=ra.w;
            c[4]+=rb.x;c[5]+=rb.y;c[6]+=rb.z;c[7]+=rb.w;
        }
        *(float4*)&crow[n0]   = make_float4(c[0],c[1],c[2],c[3]);
        *(float4*)&crow[n0+4] = make_float4(c[4],c[5],c[6],c[7]);
    }
}

// ---------------- geometry bias -------------------------------------------
__global__ __launch_bounds__(256) void bias_kernel(
    const float* __restrict__ wg_w, const float* __restrict__ wg_b,
    float* __restrict__ bias)
{
    __shared__ float sw[768];
    __shared__ float sc[12];
    int t = threadIdx.x;
    for (int i=t;i<768;i+=256) sw[i]=wg_w[i];
    __syncthreads();
    if (t < 12){
        float s = wg_b[t];
        #pragma unroll
        for (int k=48;k<64;++k) s += sw[t*64+k];   // cos(0)=1 terms
        sc[t] = s;
    }
    __syncthreads();
    size_t idx = (size_t)blockIdx.x*256u + t;
    if (idx >= (size_t)1025u*1025u) return;
    int i = (int)(idx/1025u), j = (int)(idx - (size_t)i*1025u);
    if (i==0 || j==0){
        #pragma unroll
        for (int h=0;h<12;++h) bias[(size_t)h*1025u*1025u + idx] = 0.f;
        return;
    }
    int a = i-1, b2 = j-1;
    float fx = (float)((a>>5)-(b2>>5)) * (1.0f/32.0f);
    float fy = (float)((a&31)-(b2&31)) * (1.0f/32.0f);
    const float inv_wbox = 1.0f/1.03125f;
    float dx = logf(fmaxf(fabsf(fx*inv_wbox), 0.001f));
    float dy = logf(fmaxf(fabsf(fy*inv_wbox), 0.001f));
    const float dm[8] = {1.0f, 0.42169650342f, 0.1778279410f, 0.074989420933f,
                         0.03162277660f, 0.013335214322f, 0.0056234132519f, 0.0023713737057f};
    float sx[8], cx[8], sy[8], cy[8];
    #pragma unroll
    for (int k=0;k<8;++k){
        sincosf(100.0f*dx*dm[k], &sx[k], &cx[k]);
        sincosf(100.0f*dy*dm[k], &sy[k], &cy[k]);
    }
    #pragma unroll
    for (int h=0;h<12;++h){
        const float* w = sw + h*64;
        float acc = sc[h];
        #pragma unroll
        for (int k=0;k<8;++k)
            acc += sx[k]*w[k] + sy[k]*w[8+k] + cx[k]*w[32+k] + cy[k]*w[40+k];
        float wv = fmaxf(acc, 0.0f);
        bias[(size_t)h*1025u*1025u + idx] = logf(fmaxf(wv, 1e-6f));
    }
}

// ---------------- temporal attention (T=4): one warp per (seq, head) ------
__global__ __launch_bounds__(256) void temporal_attn_kernel(
    const float* __restrict__ qkv, float* __restrict__ out)
{
    int gw = (blockIdx.x*256 + threadIdx.x) >> 5;
    int lane = threadIdx.x & 31;
    if (gw >= 2048*12) return;
    int s = gw/12, h = gw - s*12;
    size_t base = (size_t)(s*4)*2304u + h*64 + lane*2;
    float2 q[4],k[4],v[4];
    #pragma unroll
    for (int i=0;i<4;++i){
        q[i] = *(const float2*)(qkv + base + (size_t)i*2304u);
        k[i] = *(const float2*)(qkv + base + (size_t)i*2304u + 768u);
        v[i] = *(const float2*)(qkv + base + (size_t)i*2304u + 1536u);
    }
    float sc[16];
    #pragma unroll
    for (int i=0;i<4;++i)
        #pragma unroll
        for (int j=0;j<4;++j)
            sc[i*4+j] = q[i].x*k[j].x + q[i].y*k[j].y;
    #pragma unroll
    for (int t2=0;t2<16;++t2)
        #pragma unroll
        for (int off=16; off>0; off>>=1)
            sc[t2] += __shfl_xor_sync(0xffffffffu, sc[t2], off);
    #pragma unroll
    for (int i=0;i<4;++i){
        float s0=sc[i*4+0]*0.125f, s1=sc[i*4+1]*0.125f, s2=sc[i*4+2]*0.125f, s3=sc[i*4+3]*0.125f;
        float m = fmaxf(fmaxf(s0,s1),fmaxf(s2,s3));
        float e0=expf(s0-m), e1=expf(s1-m), e2=expf(s2-m), e3=expf(s3-m);
        float inv = 1.0f/(e0+e1+e2+e3);
        float ox = (e0*v[0].x + e1*v[1].x + e2*v[2].x + e3*v[3].x)*inv;
        float oy = (e0*v[0].y + e1*v[1].y + e2*v[2].y + e3*v[3].y)*inv;
        float2 o; o.x = ox; o.y = oy;
        *(float2*)(out + (size_t)(s*4+i)*768u + h*64 + lane*2) = o;
    }
}

// ---------------- spatial flash attention (f32x2 compute) ------------------
// grid (17, 96): blockIdx.x = i-tile (64 rows), blockIdx.y = bt*12+h
__global__ __launch_bounds__(256) void flash_attn_kernel(
    const float* __restrict__ qkv, const float* __restrict__ bias,
    float* __restrict__ out)
{
    extern __shared__ float sm[];
    float (*Qs)[68] = (float(*)[68])sm;            // [d][i]
    float (*Ks)[68] = (float(*)[68])(sm + 64*68);  // [d][j]
    float (*Vs)[68] = (float(*)[68])(sm + 2*64*68);// [j][d]
    float (*Ps)[68] = (float(*)[68])(sm + 3*64*68);// [i][j]
    int bh = blockIdx.y; int bt = bh/12, h = bh - bt*12;
    int i0 = blockIdx.x*64;
    int tid = threadIdx.x;
    int tx = tid & 15, ty = tid >> 4;

    #pragma unroll
    for (int u=0; u<16; ++u){
        int idx = u*256 + tid;
        int dd = idx & 63, ii = idx >> 6;
        int gi = i0 + ii;
        Qs[dd][ii] = (gi < 1025) ? qkv[(size_t)(bt*1025+gi)*2304u + h*64 + dd]*0.125f : 0.f;
    }

    float m[4], l[4];
    unsigned long long accp[4][2];   // packed pairs along d
    #pragma unroll
    for (int r=0;r<4;++r){ m[r]=-1e30f; l[r]=0.f; accp[r][0]=0ull; accp[r][1]=0ull; }

    for (int j0=0; j0<1025; j0+=64){
        #pragma unroll
        for (int u=0; u<16; ++u){
            int idx = u*256 + tid;
            int dd = idx & 63, jj = idx >> 6;
            int gj = j0 + jj;
            bool v = (gj < 1025);
            Ks[dd][jj] = v ? qkv[(size_t)(bt*1025+gj)*2304u + 768u  + h*64 + dd] : 0.f;
            Vs[jj][dd] = v ? qkv[(size_t)(bt*1025+gj)*2304u + 1536u + h*64 + dd] : 0.f;
        }
        __syncthreads();

        // S tile via packed FMA: pairs along j
        unsigned long long s2[4][2];
        #pragma unroll
        for (int r=0;r<4;++r){ s2[r][0]=0ull; s2[r][1]=0ull; }
        #pragma unroll 8
        for (int k=0;k<64;++k){
            float4 q4 = *(const float4*)&Qs[k][ty*4];
            float4 k4 = *(const float4*)&Ks[k][tx*4];
            unsigned long long kk0 = pack2(k4.x,k4.y), kk1 = pack2(k4.z,k4.w);
            float qr[4]={q4.x,q4.y,q4.z,q4.w};
            #pragma unroll
            for (int r=0;r<4;++r){
                unsigned long long qq = pack2(qr[r],qr[r]);
                fma2(s2[r][0], qq, kk0);
                fma2(s2[r][1], qq, kk1);
            }
        }
        float s[4][4];
        #pragma unroll
        for (int r=0;r<4;++r){
            unpack2(s2[r][0], s[r][0], s[r][1]);
            unpack2(s2[r][1], s[r][2], s[r][3]);
        }
        // bias + masking
        #pragma unroll
        for (int r=0;r<4;++r){
            int gi = i0 + ty*4 + r;
            #pragma unroll
            for (int c=0;c<4;++c){
                int gj = j0 + tx*4 + c;
                if (gi < 1025 && gj < 1025)
                    s[r][c] += bias[((size_t)h*1025u + gi)*1025u + gj];
                else
                    s[r][c] = -1e30f;
            }
        }
        // online softmax (row group = 16 threads of tx)
        #pragma unroll
        for (int r=0;r<4;++r){
            float rm = fmaxf(fmaxf(s[r][0],s[r][1]),fmaxf(s[r][2],s[r][3]));
            #pragma unroll
            for (int o=8;o>0;o>>=1) rm = fmaxf(rm, __shfl_xor_sync(0xffffffffu, rm, o));
            float mn = fmaxf(m[r], rm);
            float corr = __expf(m[r]-mn);
            m[r] = mn;
            float rs = 0.f;
            #pragma unroll
            for (int c=0;c<4;++c){ float p = __expf(s[r][c]-mn); s[r][c]=p; rs+=p; }
            #pragma unroll
            for (int o=8;o>0;o>>=1) rs += __shfl_xor_sync(0xffffffffu, rs, o);
            l[r] = l[r]*corr + rs;
            unsigned long long cc = pack2(corr,corr);
            mul2ip(accp[r][0], cc);
            mul2ip(accp[r][1], cc);
        }
        __syncthreads();
        #pragma unroll
        for (int r=0;r<4;++r)
            *(float4*)&Ps[ty*4+r][tx*4] = make_float4(s[r][0],s[r][1],s[r][2],s[r][3]);
        __syncthreads();
        // acc += P @ V (packed along d)
        #pragma unroll 8
        for (int jj=0;jj<64;++jj){
            float4 v4 = *(const float4*)&Vs[jj][tx*4];
            unsigned long long vv0 = pack2(v4.x,v4.y), vv1 = pack2(v4.z,v4.w);
            #pragma unroll
            for (int r=0;r<4;++r){
                float p = Ps[ty*4+r][jj];
                unsigned long long pp = pack2(p,p);
                fma2(accp[r][0], pp, vv0);
                fma2(accp[r][1], pp, vv1);
            }
        }
        __syncthreads();
    }
    #pragma unroll
    for (int r=0;r<4;++r){
        int gi = i0 + ty*4 + r;
        if (gi < 1025){
            float inv = 1.0f/l[r];
            float a0,a1,a2,a3;
            unpack2(accp[r][0], a0, a1);
            unpack2(accp[r][1], a2, a3);
            *(float4*)&out[(size_t)(bt*1025+gi)*768u + h*64 + tx*4]
                = make_float4(a0*inv, a1*inv, a2*inv, a3*inv);
        }
    }
}

// ---------------- combine: xout = concat(cls,xt) + concat(cls_out,res_s) ---
__global__ __launch_bounds__(256) void combine_kernel(
    const float* __restrict__ x, const float* __restrict__ xt,
    const float* __restrict__ res_s, float* __restrict__ out)
{
    size_t idx = (size_t)blockIdx.x*256u + threadIdx.x;
    if (idx >= (size_t)2u*4097u*768u) return;
    int c = (int)(idx % 768u);
    size_t row = idx / 768u;
    int b = (int)(row / 4097u);
    int rr = (int)(row - (size_t)b*4097u);
    float v;
    if (rr == 0){
        float s = 0.f;
        #pragma unroll
        for (int t2=0;t2<4;++t2)
            s += res_s[((size_t)((b*4+t2)*1025))*768u + c];
        v = x[row*768u + c] + 0.25f*s;
    } else {
        int qq = rr-1; int n = qq>>2, t2 = qq&3;
        v = xt[((size_t)(b*4096 + qq))*768u + c]
          + res_s[((size_t)((b*4+t2)*1025 + 1 + n))*768u + c];
    }
    out[row*768u + c] = v;
}

// ---------------- launcher -------------------------------------------------
extern "C" void kernel_launch(void* const* d_in, const int* in_sizes, int n_in,
                              void* d_out, int out_size)
{
    const float* x       = (const float*)d_in[0];
    const float* norm1_g = (const float*)d_in[1];
    const float* norm1_b = (const float*)d_in[2];
    const float* qkv_w   = (const float*)d_in[3];
    const float* proj_w  = (const float*)d_in[4];
    const float* proj_b  = (const float*)d_in[5];
    const float* wg_w    = (const float*)d_in[6];
    const float* wg_b    = (const float*)d_in[7];
    const float* tnorm1_g= (const float*)d_in[8];
    const float* tnorm1_b= (const float*)d_in[9];
    const float* tqkv_w  = (const float*)d_in[10];
    const float* tproj_w = (const float*)d_in[11];
    const float* tproj_b = (const float*)d_in[12];
    const float* tfc_w   = (const float*)d_in[13];
    const float* tfc_b   = (const float*)d_in[14];
    const float* norm2_g = (const float*)d_in[15];
    const float* norm2_b = (const float*)d_in[16];
    const float* fc1_w   = (const float*)d_in[17];
    const float* fc1_b   = (const float*)d_in[18];
    const float* fc2_w   = (const float*)d_in[19];
    const float* fc2_b   = (const float*)d_in[20];
    float* out = (float*)d_out;

    float* base = nullptr;
    cudaGetSymbolAddress((void**)&base, g_scratch);
    float* p_ln   = base + OFF_LN;
    float* p_qkv  = base + OFF_QKV;
    float* p_att  = base + OFF_ATT;
    float* p_res  = base + OFF_RES;
    float* p_xt   = base + OFF_XT;
    float* p_bias = base + OFF_BIAS;
    float* p_h    = base + OFF_H;

    const int FLASH_SMEM = 4*64*68*4;  // 69,632 B
    cudaFuncSetAttribute(flash_attn_kernel,
                         cudaFuncAttributeMaxDynamicSharedMemorySize, FLASH_SMEM);

    // ---- temporal branch ----
    ln_kernel<<<8192,256>>>(nullptr, x, p_ln, tnorm1_g, tnorm1_b, 1);
    sgemm_nt<<<dim3(18,64),256>>>(p_ln, tqkv_w, nullptr, p_qkv, 8192, 2304, 768, nullptr, 0, 0);
    temporal_attn_kernel<<<3072,256>>>(p_qkv, p_att);
    sgemm_nt<<<dim3(6,64),256>>>(p_att, tproj_w, tproj_b, p_res, 8192, 768, 768, nullptr, 0, 0);
    sgemm_nt<<<dim3(6,64),256>>>(p_res, tfc_w, tfc_b, p_xt, 8192, 768, 768, x, 2, 0); // xt = x[:,1:] + res

    // ---- spatial branch ----
    ln_kernel<<<8200,256>>>(p_xt, x, p_ln, norm1_g, norm1_b, 2);
    sgemm_nt<<<dim3(18,65),256>>>(p_ln, qkv_w, nullptr, p_qkv, 8200, 2304, 768, nullptr, 0, 0);
    bias_kernel<<<4105,256>>>(wg_w, wg_b, p_bias);
    flash_attn_kernel<<<dim3(17,96),256,FLASH_SMEM>>>(p_qkv, p_bias, p_att);
    sgemm_nt<<<dim3(6,65),256>>>(p_att, proj_w, proj_b, p_res, 8200, 768, 768, nullptr, 0, 0);
    combine_kernel<<<24582,256>>>(x, p_xt, p_res, out);

    // ---- MLP (chunked over 2x4097 rows) ----
    ln_kernel<<<8194,256>>>(out, nullptr, p_ln, norm2_g, norm2_b, 0);
    for (int ch=0; ch<2; ++ch){
        size_t ro = (size_t)ch*4097u;
        sgemm_nt<<<dim3(24,33),256>>>(p_ln + ro*768u, fc1_w, fc1_b, p_h, 4097, 3072, 768, nullptr, 0, 1);
        sgemm_nt<<<dim3(6,33),256>>>(p_h, fc2_w, fc2_b, out + ro*768u, 4097, 768, 3072, out + ro*768u, 1, 0);
    }
}

// round 7
// speedup vs baseline: 1.8538x; 1.7914x over previous
#include <cuda_runtime.h>
#include <cuda_bf16.h>
#include <math.h>
#include <stdint.h>

// ---------------- consolidated scratch (single symbol, ~317MB) -------------
#define OFF_LN      0ull
#define OFF_QKV     6297600ull
#define OFF_ATT     25190400ull
#define OFF_RES     31488000ull
#define OFF_XT      37785600ull
#define OFF_BIAS    44077056ull
#define OFF_H       56684560ull
#define OFF_WBF     69270544ull
#define SCRATCH_TOTAL 79297552ull
__device__ float g_scratch[SCRATCH_TOTAL];

// bf16 weight offsets (in bf16 elements, hi then lo contiguous)
#define WO_TQKV  0u
#define WO_QKV   3538944u
#define WO_TPROJ 7077888u
#define WO_PROJ  8257536u
#define WO_TFC   9437184u
#define WO_FC1   10616832u
#define WO_FC2   15335424u

__device__ __forceinline__ float gelu_exact(float x){
    return 0.5f*x*(1.0f+erff(x*0.70710678118654752440f));
}

// ---------------- weight fp32 -> bf16 hi/lo conversion ---------------------
__global__ __launch_bounds__(256) void wconv_kernel(
    const float* __restrict__ w, __nv_bfloat16* __restrict__ hi,
    __nv_bfloat16* __restrict__ lo, int n)
{
    for (int i = blockIdx.x*256 + threadIdx.x; i < n; i += gridDim.x*256){
        float v = w[i];
        __nv_bfloat16 h = __float2bfloat16(v);
        hi[i] = h;
        lo[i] = __float2bfloat16(v - __bfloat162float(h));
    }
}

// ---------------- HMMA (mma.sync) split-bf16 GEMM --------------------------
// C[M,N] = A[M,K] @ W[N,K]^T  with A,W split into bf16 hi/lo, 3 products.
// 256 thr = 8 warps (2x4), CTA tile 128x128, warp tile 64x32, K chunk 32.
__device__ __forceinline__ void mma_bf16(float* d, const uint32_t* a, const uint32_t* b){
    asm volatile("mma.sync.aligned.m16n8k16.row.col.f32.bf16.bf16.f32 "
        "{%0,%1,%2,%3}, {%4,%5,%6,%7}, {%8,%9}, {%0,%1,%2,%3};"
        : "+f"(d[0]), "+f"(d[1]), "+f"(d[2]), "+f"(d[3])
        : "r"(a[0]), "r"(a[1]), "r"(a[2]), "r"(a[3]), "r"(b[0]), "r"(b[1]));
}

#define TG_SMEM (4*128*40*2)   // 40960 bytes

__global__ __launch_bounds__(256) void tgemm_nt(
    const float* __restrict__ A,
    const __nv_bfloat16* __restrict__ Whi, const __nv_bfloat16* __restrict__ Wlo,
    const float* __restrict__ bias, float* __restrict__ C,
    int M, int N, int K,
    const float* __restrict__ res, int resMode, int doGelu)
{
    extern __shared__ __nv_bfloat16 smem[];
    __nv_bfloat16* Ah = smem;               // [128][40]
    __nv_bfloat16* Al = smem + 5120;
    __nv_bfloat16* Bh = smem + 10240;
    __nv_bfloat16* Bl = smem + 15360;

    int tid = threadIdx.x;
    int wid = tid >> 5, lane = tid & 31;
    int warpM = wid >> 2, warpN = wid & 3;
    int g = lane >> 2, tg = lane & 3;
    int bm = blockIdx.y*128, bn = blockIdx.x*128;

    float acc[4][4][4];
    #pragma unroll
    for (int i=0;i<4;++i)
        #pragma unroll
        for (int j=0;j<4;++j)
            #pragma unroll
            for (int q=0;q<4;++q) acc[i][j][q]=0.f;

    int NC = K >> 5;
    for (int c = 0; c < NC; ++c){
        int k0 = c << 5;
        __syncthreads();
        // ---- stage A: 128 x 32 fp32 -> hi/lo bf16 ----
        #pragma unroll
        for (int u = 0; u < 4; ++u){
            int idx = u*256 + tid;          // 0..1023
            int row = idx >> 3;
            int cq  = (idx & 7) << 2;
            int gm = bm + row;
            float4 v = (gm < M) ? *(const float4*)(A + (size_t)gm*K + k0 + cq)
                                : make_float4(0.f,0.f,0.f,0.f);
            __nv_bfloat16 hx=__float2bfloat16(v.x), hy=__float2bfloat16(v.y),
                          hz=__float2bfloat16(v.z), hw=__float2bfloat16(v.w);
            __nv_bfloat16 lx=__float2bfloat16(v.x-__bfloat162float(hx)),
                          ly=__float2bfloat16(v.y-__bfloat162float(hy)),
                          lz=__float2bfloat16(v.z-__bfloat162float(hz)),
                          lw=__float2bfloat16(v.w-__bfloat162float(hw));
            __nv_bfloat162 h01=__halves2bfloat162(hx,hy), h23=__halves2bfloat162(hz,hw);
            __nv_bfloat162 l01=__halves2bfloat162(lx,ly), l23=__halves2bfloat162(lz,lw);
            int e = row*40 + cq;
            *(__nv_bfloat162*)&Ah[e]   = h01;
            *(__nv_bfloat162*)&Ah[e+2] = h23;
            *(__nv_bfloat162*)&Al[e]   = l01;
            *(__nv_bfloat162*)&Al[e+2] = l23;
        }
        // ---- stage B: 128 x 32 bf16 (hi & lo preconverted) ----
        #pragma unroll
        for (int u = 0; u < 4; ++u){
            int idx = u*256 + tid;          // 0..1023
            int sel = idx >> 9;             // 0 = hi, 1 = lo
            int rem = idx & 511;
            int row = rem >> 2;
            int q = rem & 3;
            int gn = bn + row;
            const __nv_bfloat16* src = sel ? Wlo : Whi;
            uint4 v = *(const uint4*)(src + (size_t)gn*K + k0 + q*8);
            __nv_bfloat16* dst = sel ? Bl : Bh;
            *(uint4*)&dst[row*40 + q*8] = v;
        }
        __syncthreads();
        // ---- compute: 2 k-steps of 16 ----
        #pragma unroll
        for (int ks = 0; ks < 2; ++ks){
            int kb = ks*16 + tg*2;
            uint32_t ahi[4][4], alo[4][4];
            #pragma unroll
            for (int i=0;i<4;++i){
                int r0 = warpM*64 + i*16 + g;
                ahi[i][0] = *(const uint32_t*)&Ah[r0*40 + kb];
                ahi[i][1] = *(const uint32_t*)&Ah[(r0+8)*40 + kb];
                ahi[i][2] = *(const uint32_t*)&Ah[r0*40 + kb + 8];
                ahi[i][3] = *(const uint32_t*)&Ah[(r0+8)*40 + kb + 8];
                alo[i][0] = *(const uint32_t*)&Al[r0*40 + kb];
                alo[i][1] = *(const uint32_t*)&Al[(r0+8)*40 + kb];
                alo[i][2] = *(const uint32_t*)&Al[r0*40 + kb + 8];
                alo[i][3] = *(const uint32_t*)&Al[(r0+8)*40 + kb + 8];
            }
            uint32_t bhi[4][2], blo[4][2];
            #pragma unroll
            for (int j=0;j<4;++j){
                int n0 = warpN*32 + j*8 + g;
                bhi[j][0] = *(const uint32_t*)&Bh[n0*40 + kb];
                bhi[j][1] = *(const uint32_t*)&Bh[n0*40 + kb + 8];
                blo[j][0] = *(const uint32_t*)&Bl[n0*40 + kb];
                blo[j][1] = *(const uint32_t*)&Bl[n0*40 + kb + 8];
            }
            #pragma unroll
            for (int i=0;i<4;++i)
                #pragma unroll
                for (int j=0;j<4;++j){
                    mma_bf16(acc[i][j], ahi[i], bhi[j]);
                    mma_bf16(acc[i][j], ahi[i], blo[j]);
                    mma_bf16(acc[i][j], alo[i], bhi[j]);
                }
        }
    }

    // ---- epilogue (fragment layout: rows g/g+8, cols tg*2/tg*2+1) ----
    #pragma unroll
    for (int i=0;i<4;++i){
        #pragma unroll
        for (int half=0; half<2; ++half){
            int m = bm + warpM*64 + i*16 + g + half*8;
            if (m >= M) continue;
            const float* rrow = nullptr;
            if (resMode == 1) rrow = res + (size_t)m*N;
            else if (resMode == 2){ int bb = m>>12, jj = m&4095; rrow = res + (size_t)(bb*4097+1+jj)*N; }
            float* crow = C + (size_t)m*N;
            #pragma unroll
            for (int j=0;j<4;++j){
                int n0 = bn + warpN*32 + j*8 + tg*2;
                float v0 = acc[i][j][half*2+0];
                float v1 = acc[i][j][half*2+1];
                if (bias){ float2 bv = *(const float2*)&bias[n0]; v0 += bv.x; v1 += bv.y; }
                if (doGelu){ v0 = gelu_exact(v0); v1 = gelu_exact(v1); }
                if (rrow){ float2 rv = *(const float2*)&rrow[n0]; v0 += rv.x; v1 += rv.y; }
                *(float2*)&crow[n0] = make_float2(v0, v1);
            }
        }
    }
}

// ---------------- layernorm with gather modes ------------------------------
__global__ __launch_bounds__(256) void ln_kernel(
    const float* __restrict__ src, const float* __restrict__ xsrc,
    float* __restrict__ dst, const float* __restrict__ g, const float* __restrict__ b,
    int mode)
{
    __shared__ float red[8];
    int r = blockIdx.x;
    int t = threadIdx.x;
    int lane = t & 31, warp = t >> 5;
    const float* in; size_t base;
    if (mode == 0){ in = src; base = (size_t)r*768u; }
    else if (mode == 1){ int bb = r>>12; int j = r & 4095; in = xsrc; base = (size_t)(bb*4097 + 1 + j)*768u; }
    else {
        int bt = r/1025, pos = r - bt*1025;
        int bb = bt>>2, tt = bt&3;
        if (pos == 0){ in = xsrc; base = (size_t)(bb*4097)*768u; }
        else { int n = pos-1; in = src; base = (size_t)(bb*4096 + n*4 + tt)*768u; }
    }
    float v0 = in[base+t], v1 = in[base+t+256], v2 = in[base+t+512];
    float s = v0+v1+v2;
    #pragma unroll
    for (int o=16;o>0;o>>=1) s += __shfl_xor_sync(0xffffffffu, s, o);
    if (lane==0) red[warp]=s;
    __syncthreads();
    if (warp==0){
        float w = red[lane&7];
        #pragma unroll
        for (int o=4;o>0;o>>=1) w += __shfl_xor_sync(0xffffffffu, w, o);
        if (lane==0) red[0]=w;
    }
    __syncthreads();
    float mean = red[0]*(1.0f/768.0f);
    float d0=v0-mean, d1=v1-mean, d2=v2-mean;
    float q = d0*d0+d1*d1+d2*d2;
    #pragma unroll
    for (int o=16;o>0;o>>=1) q += __shfl_xor_sync(0xffffffffu, q, o);
    __syncthreads();
    if (lane==0) red[warp]=q;
    __syncthreads();
    if (warp==0){
        float w = red[lane&7];
        #pragma unroll
        for (int o=4;o>0;o>>=1) w += __shfl_xor_sync(0xffffffffu, w, o);
        if (lane==0) red[0]=w;
    }
    __syncthreads();
    float var = red[0]*(1.0f/768.0f);
    float rstd = rsqrtf(var + 1e-5f);
    size_t ob = (size_t)r*768u;
    dst[ob+t]     = d0*rstd*g[t]     + b[t];
    dst[ob+t+256] = d1*rstd*g[t+256] + b[t+256];
    dst[ob+t+512] = d2*rstd*g[t+512] + b[t+512];
}

// ---------------- geometry bias -------------------------------------------
__global__ __launch_bounds__(256) void bias_kernel(
    const float* __restrict__ wg_w, const float* __restrict__ wg_b,
    float* __restrict__ bias)
{
    __shared__ float sw[768];
    __shared__ float sc[12];
    int t = threadIdx.x;
    for (int i=t;i<768;i+=256) sw[i]=wg_w[i];
    __syncthreads();
    if (t < 12){
        float s = wg_b[t];
        #pragma unroll
        for (int k=48;k<64;++k) s += sw[t*64+k];
        sc[t] = s;
    }
    __syncthreads();
    size_t idx = (size_t)blockIdx.x*256u + t;
    if (idx >= (size_t)1025u*1025u) return;
    int i = (int)(idx/1025u), j = (int)(idx - (size_t)i*1025u);
    if (i==0 || j==0){
        #pragma unroll
        for (int h=0;h<12;++h) bias[(size_t)h*1025u*1025u + idx] = 0.f;
        return;
    }
    int a = i-1, b2 = j-1;
    float fx = (float)((a>>5)-(b2>>5)) * (1.0f/32.0f);
    float fy = (float)((a&31)-(b2&31)) * (1.0f/32.0f);
    const float inv_wbox = 1.0f/1.03125f;
    float dx = logf(fmaxf(fabsf(fx*inv_wbox), 0.001f));
    float dy = logf(fmaxf(fabsf(fy*inv_wbox), 0.001f));
    const float dm[8] = {1.0f, 0.42169650342f, 0.1778279410f, 0.074989420933f,
                         0.03162277660f, 0.013335214322f, 0.0056234132519f, 0.0023713737057f};
    float sx[8], cx[8], sy[8], cy[8];
    #pragma unroll
    for (int k=0;k<8;++k){
        sincosf(100.0f*dx*dm[k], &sx[k], &cx[k]);
        sincosf(100.0f*dy*dm[k], &sy[k], &cy[k]);
    }
    #pragma unroll
    for (int h=0;h<12;++h){
        const float* w = sw + h*64;
        float acc = sc[h];
        #pragma unroll
        for (int k=0;k<8;++k)
            acc += sx[k]*w[k] + sy[k]*w[8+k] + cx[k]*w[32+k] + cy[k]*w[40+k];
        float wv = fmaxf(acc, 0.0f);
        bias[(size_t)h*1025u*1025u + idx] = logf(fmaxf(wv, 1e-6f));
    }
}

// ---------------- temporal attention (T=4): one warp per (seq, head) ------
__global__ __launch_bounds__(256) void temporal_attn_kernel(
    const float* __restrict__ qkv, float* __restrict__ out)
{
    int gw = (blockIdx.x*256 + threadIdx.x) >> 5;
    int lane = threadIdx.x & 31;
    if (gw >= 2048*12) return;
    int s = gw/12, h = gw - s*12;
    size_t base = (size_t)(s*4)*2304u + h*64 + lane*2;
    float2 q[4],k[4],v[4];
    #pragma unroll
    for (int i=0;i<4;++i){
        q[i] = *(const float2*)(qkv + base + (size_t)i*2304u);
        k[i] = *(const float2*)(qkv + base + (size_t)i*2304u + 768u);
        v[i] = *(const float2*)(qkv + base + (size_t)i*2304u + 1536u);
    }
    float sc[16];
    #pragma unroll
    for (int i=0;i<4;++i)
        #pragma unroll
        for (int j=0;j<4;++j)
            sc[i*4+j] = q[i].x*k[j].x + q[i].y*k[j].y;
    #pragma unroll
    for (int t2=0;t2<16;++t2)
        #pragma unroll
        for (int off=16; off>0; off>>=1)
            sc[t2] += __shfl_xor_sync(0xffffffffu, sc[t2], off);
    #pragma unroll
    for (int i=0;i<4;++i){
        float s0=sc[i*4+0]*0.125f, s1=sc[i*4+1]*0.125f, s2=sc[i*4+2]*0.125f, s3=sc[i*4+3]*0.125f;
        float m = fmaxf(fmaxf(s0,s1),fmaxf(s2,s3));
        float e0=expf(s0-m), e1=expf(s1-m), e2=expf(s2-m), e3=expf(s3-m);
        float inv = 1.0f/(e0+e1+e2+e3);
        float ox = (e0*v[0].x + e1*v[1].x + e2*v[2].x + e3*v[3].x)*inv;
        float oy = (e0*v[0].y + e1*v[1].y + e2*v[2].y + e3*v[3].y)*inv;
        float2 o; o.x = ox; o.y = oy;
        *(float2*)(out + (size_t)(s*4+i)*768u + h*64 + lane*2) = o;
    }
}

// ---------------- spatial flash attention ----------------------------------
__global__ __launch_bounds__(256) void flash_attn_kernel(
    const float* __restrict__ qkv, const float* __restrict__ bias,
    float* __restrict__ out)
{
    extern __shared__ float sm[];
    float (*Qs)[68] = (float(*)[68])sm;
    float (*Ks)[68] = (float(*)[68])(sm + 64*68);
    float (*Vs)[68] = (float(*)[68])(sm + 2*64*68);
    float (*Ps)[68] = (float(*)[68])(sm + 3*64*68);
    int bh = blockIdx.y; int bt = bh/12, h = bh - bt*12;
    int i0 = blockIdx.x*64;
    int tid = threadIdx.x;
    int tx = tid & 15, ty = tid >> 4;

    #pragma unroll
    for (int u=0; u<16; ++u){
        int idx = u*256 + tid;
        int dd = idx & 63, ii = idx >> 6;
        int gi = i0 + ii;
        Qs[dd][ii] = (gi < 1025) ? qkv[(size_t)(bt*1025+gi)*2304u + h*64 + dd]*0.125f : 0.f;
    }

    float m[4], l[4], acc[4][4];
    #pragma unroll
    for (int r=0;r<4;++r){ m[r]=-1e30f; l[r]=0.f;
        #pragma unroll
        for (int c=0;c<4;++c) acc[r][c]=0.f; }

    for (int j0=0; j0<1025; j0+=64){
        #pragma unroll
        for (int u=0; u<16; ++u){
            int idx = u*256 + tid;
            int dd = idx & 63, jj = idx >> 6;
            int gj = j0 + jj;
            bool v = (gj < 1025);
            Ks[dd][jj] = v ? qkv[(size_t)(bt*1025+gj)*2304u + 768u  + h*64 + dd] : 0.f;
            Vs[jj][dd] = v ? qkv[(size_t)(bt*1025+gj)*2304u + 1536u + h*64 + dd] : 0.f;
        }
        __syncthreads();

        float s[4][4];
        #pragma unroll
        for (int r=0;r<4;++r)
            #pragma unroll
            for (int c=0;c<4;++c) s[r][c]=0.f;
        #pragma unroll 8
        for (int k=0;k<64;++k){
            float4 q4 = *(const float4*)&Qs[k][ty*4];
            float4 k4 = *(const float4*)&Ks[k][tx*4];
            float qr[4]={q4.x,q4.y,q4.z,q4.w}, kc[4]={k4.x,k4.y,k4.z,k4.w};
            #pragma unroll
            for (int r=0;r<4;++r)
                #pragma unroll
                for (int c=0;c<4;++c) s[r][c] += qr[r]*kc[c];
        }
        #pragma unroll
        for (int r=0;r<4;++r){
            int gi = i0 + ty*4 + r;
            #pragma unroll
            for (int c=0;c<4;++c){
                int gj = j0 + tx*4 + c;
                if (gi < 1025 && gj < 1025)
                    s[r][c] += bias[((size_t)h*1025u + gi)*1025u + gj];
                else
                    s[r][c] = -1e30f;
            }
        }
        #pragma unroll
        for (int r=0;r<4;++r){
            float rm = fmaxf(fmaxf(s[r][0],s[r][1]),fmaxf(s[r][2],s[r][3]));
            #pragma unroll
            for (int o=8;o>0;o>>=1) rm = fmaxf(rm, __shfl_xor_sync(0xffffffffu, rm, o));
            float mn = fmaxf(m[r], rm);
            float corr = __expf(m[r]-mn);
            m[r] = mn;
            float rs = 0.f;
            #pragma unroll
            for (int c=0;c<4;++c){ float p = __expf(s[r][c]-mn); s[r][c]=p; rs+=p; }
            #pragma unroll
            for (int o=8;o>0;o>>=1) rs += __shfl_xor_sync(0xffffffffu, rs, o);
            l[r] = l[r]*corr + rs;
            #pragma unroll
            for (int c=0;c<4;++c) acc[r][c] *= corr;
        }
        __syncthreads();
        #pragma unroll
        for (int r=0;r<4;++r)
            *(float4*)&Ps[ty*4+r][tx*4] = make_float4(s[r][0],s[r][1],s[r][2],s[r][3]);
        __syncthreads();
        #pragma unroll 8
        for (int jj=0;jj<64;++jj){
            float4 v4 = *(const float4*)&Vs[jj][tx*4];
            #pragma unroll
            for (int r=0;r<4;++r){
                float p = Ps[ty*4+r][jj];
                acc[r][0] += p*v4.x; acc[r][1] += p*v4.y;
                acc[r][2] += p*v4.z; acc[r][3] += p*v4.w;
            }
        }
        __syncthreads();
    }
    #pragma unroll
    for (int r=0;r<4;++r){
        int gi = i0 + ty*4 + r;
        if (gi < 1025){
            float inv = 1.0f/l[r];
            *(float4*)&out[(size_t)(bt*1025+gi)*768u + h*64 + tx*4]
                = make_float4(acc[r][0]*inv, acc[r][1]*inv, acc[r][2]*inv, acc[r][3]*inv);
        }
    }
}

// ---------------- combine -------------------------------------------------
__global__ __launch_bounds__(256) void combine_kernel(
    const float* __restrict__ x, const float* __restrict__ xt,
    const float* __restrict__ res_s, float* __restrict__ out)
{
    size_t idx = (size_t)blockIdx.x*256u + threadIdx.x;
    if (idx >= (size_t)2u*4097u*768u) return;
    int c = (int)(idx % 768u);
    size_t row = idx / 768u;
    int b = (int)(row / 4097u);
    int rr = (int)(row - (size_t)b*4097u);
    float v;
    if (rr == 0){
        float s = 0.f;
        #pragma unroll
        for (int t2=0;t2<4;++t2)
            s += res_s[((size_t)((b*4+t2)*1025))*768u + c];
        v = x[row*768u + c] + 0.25f*s;
    } else {
        int qq = rr-1; int n = qq>>2, t2 = qq&3;
        v = xt[((size_t)(b*4096 + qq))*768u + c]
          + res_s[((size_t)((b*4+t2)*1025 + 1 + n))*768u + c];
    }
    out[row*768u + c] = v;
}

// ---------------- launcher -------------------------------------------------
extern "C" void kernel_launch(void* const* d_in, const int* in_sizes, int n_in,
                              void* d_out, int out_size)
{
    const float* x       = (const float*)d_in[0];
    const float* norm1_g = (const float*)d_in[1];
    const float* norm1_b = (const float*)d_in[2];
    const float* qkv_w   = (const float*)d_in[3];
    const float* proj_w  = (const float*)d_in[4];
    const float* proj_b  = (const float*)d_in[5];
    const float* wg_w    = (const float*)d_in[6];
    const float* wg_b    = (const float*)d_in[7];
    const float* tnorm1_g= (const float*)d_in[8];
    const float* tnorm1_b= (const float*)d_in[9];
    const float* tqkv_w  = (const float*)d_in[10];
    const float* tproj_w = (const float*)d_in[11];
    const float* tproj_b = (const float*)d_in[12];
    const float* tfc_w   = (const float*)d_in[13];
    const float* tfc_b   = (const float*)d_in[14];
    const float* norm2_g = (const float*)d_in[15];
    const float* norm2_b = (const float*)d_in[16];
    const float* fc1_w   = (const float*)d_in[17];
    const float* fc1_b   = (const float*)d_in[18];
    const float* fc2_w   = (const float*)d_in[19];
    const float* fc2_b   = (const float*)d_in[20];
    float* out = (float*)d_out;

    float* base = nullptr;
    cudaGetSymbolAddress((void**)&base, g_scratch);
    float* p_ln   = base + OFF_LN;
    float* p_qkv  = base + OFF_QKV;
    float* p_att  = base + OFF_ATT;
    float* p_res  = base + OFF_RES;
    float* p_xt   = base + OFF_XT;
    float* p_bias = base + OFF_BIAS;
    float* p_h    = base + OFF_H;
    __nv_bfloat16* wb = (__nv_bfloat16*)(base + OFF_WBF);

    const int FLASH_SMEM = 4*64*68*4;
    cudaFuncSetAttribute(flash_attn_kernel,
                         cudaFuncAttributeMaxDynamicSharedMemorySize, FLASH_SMEM);

    // ---- weight bf16 hi/lo conversion ----
    wconv_kernel<<<1024,256>>>(tqkv_w, wb+WO_TQKV, wb+WO_TQKV+1769472u, 1769472);
    wconv_kernel<<<1024,256>>>(qkv_w,  wb+WO_QKV,  wb+WO_QKV +1769472u, 1769472);
    wconv_kernel<<<512,256>>>(tproj_w, wb+WO_TPROJ,wb+WO_TPROJ+589824u, 589824);
    wconv_kernel<<<512,256>>>(proj_w,  wb+WO_PROJ, wb+WO_PROJ +589824u, 589824);
    wconv_kernel<<<512,256>>>(tfc_w,   wb+WO_TFC,  wb+WO_TFC  +589824u, 589824);
    wconv_kernel<<<1024,256>>>(fc1_w,  wb+WO_FC1,  wb+WO_FC1 +2359296u, 2359296);
    wconv_kernel<<<1024,256>>>(fc2_w,  wb+WO_FC2,  wb+WO_FC2 +2359296u, 2359296);

    // ---- temporal branch ----
    ln_kernel<<<8192,256>>>(nullptr, x, p_ln, tnorm1_g, tnorm1_b, 1);
    tgemm_nt<<<dim3(18,64),256,TG_SMEM>>>(p_ln, wb+WO_TQKV, wb+WO_TQKV+1769472u, nullptr, p_qkv, 8192, 2304, 768, nullptr, 0, 0);
    temporal_attn_kernel<<<3072,256>>>(p_qkv, p_att);
    tgemm_nt<<<dim3(6,64),256,TG_SMEM>>>(p_att, wb+WO_TPROJ, wb+WO_TPROJ+589824u, tproj_b, p_res, 8192, 768, 768, nullptr, 0, 0);
    tgemm_nt<<<dim3(6,64),256,TG_SMEM>>>(p_res, wb+WO_TFC, wb+WO_TFC+589824u, tfc_b, p_xt, 8192, 768, 768, x, 2, 0);

    // ---- spatial branch ----
    ln_kernel<<<8200,256>>>(p_xt, x, p_ln, norm1_g, norm1_b, 2);
    tgemm_nt<<<dim3(18,65),256,TG_SMEM>>>(p_ln, wb+WO_QKV, wb+WO_QKV+1769472u, nullptr, p_qkv, 8200, 2304, 768, nullptr, 0, 0);
    bias_kernel<<<4105,256>>>(wg_w, wg_b, p_bias);
    flash_attn_kernel<<<dim3(17,96),256,FLASH_SMEM>>>(p_qkv, p_bias, p_att);
    tgemm_nt<<<dim3(6,65),256,TG_SMEM>>>(p_att, wb+WO_PROJ, wb+WO_PROJ+589824u, proj_b, p_res, 8200, 768, 768, nullptr, 0, 0);
    combine_kernel<<<24582,256>>>(x, p_xt, p_res, out);

    // ---- MLP (chunked over 2x4097 rows) ----
    ln_kernel<<<8194,256>>>(out, nullptr, p_ln, norm2_g, norm2_b, 0);
    for (int ch=0; ch<2; ++ch){
        size_t ro = (size_t)ch*4097u;
        tgemm_nt<<<dim3(24,33),256,TG_SMEM>>>(p_ln + ro*768u, wb+WO_FC1, wb+WO_FC1+2359296u, fc1_b, p_h, 4097, 3072, 768, nullptr, 0, 1);
        tgemm_nt<<<dim3(6,33),256,TG_SMEM>>>(p_h, wb+WO_FC2, wb+WO_FC2+2359296u, fc2_b, out + ro*768u, 4097, 768, 3072, out + ro*768u, 1, 0);
    }
}